// round 5
// baseline (speedup 1.0000x reference)
#include <cuda_runtime.h>
#include <cuda_bf16.h>
#include <cstdint>

// Problem constants
#define BB   4
#define CC   2048
#define EE   1024
#define HH   16
#define DD   64
#define HDIM 1024
#define MM   (BB*CC)        // 8192

// ---------------- scratch (device globals; no allocs allowed) ----------------
__device__ __nv_bfloat16 g_xhi[MM * EE];
__device__ __nv_bfloat16 g_xlo[MM * EE];
__device__ __nv_bfloat16 g_hhi[MM * HDIM];
__device__ __nv_bfloat16 g_hlo[MM * HDIM];
__device__ __nv_bfloat16 g_wthi[4][EE * HDIM];   // transposed weights [N,K] bf16 hi
__device__ __nv_bfloat16 g_wtlo[4][EE * HDIM];   // transposed weights [N,K] bf16 lo
// Q/K/V in [b, h, c, d] layout, bf16 hi/lo
__device__ __nv_bfloat16 g_Qhi[MM * HDIM];
__device__ __nv_bfloat16 g_Qlo[MM * HDIM];
__device__ __nv_bfloat16 g_Khi[MM * HDIM];
__device__ __nv_bfloat16 g_Klo[MM * HDIM];
__device__ __nv_bfloat16 g_Vhi[MM * HDIM];
__device__ __nv_bfloat16 g_Vlo[MM * HDIM];

// ---------------- helpers ----------------
__device__ __forceinline__ uint32_t smem_u32(const void* p) {
    uint32_t a;
    asm("{ .reg .u64 t; cvta.to.shared.u64 t, %1; cvt.u32.u64 %0, t; }" : "=r"(a) : "l"(p));
    return a;
}
__device__ __forceinline__ void cp_async16(uint32_t saddr, const void* gaddr) {
    asm volatile("cp.async.cg.shared.global [%0], [%1], 16;" :: "r"(saddr), "l"(gaddr));
}
#define CP_COMMIT() asm volatile("cp.async.commit_group;" ::: "memory")

__device__ __forceinline__ void ldsm4(uint32_t r[4], uint32_t addr) {
    asm volatile("ldmatrix.sync.aligned.m8n8.x4.shared.b16 {%0,%1,%2,%3}, [%4];"
                 : "=r"(r[0]), "=r"(r[1]), "=r"(r[2]), "=r"(r[3]) : "r"(addr));
}
__device__ __forceinline__ void ldsm4t(uint32_t r[4], uint32_t addr) {
    asm volatile("ldmatrix.sync.aligned.m8n8.x4.trans.shared.b16 {%0,%1,%2,%3}, [%4];"
                 : "=r"(r[0]), "=r"(r[1]), "=r"(r[2]), "=r"(r[3]) : "r"(addr));
}
__device__ __forceinline__ void mma16816(float c[4], const uint32_t a[4],
                                         uint32_t b0, uint32_t b1) {
    asm volatile(
        "mma.sync.aligned.m16n8k16.row.col.f32.bf16.bf16.f32 "
        "{%0,%1,%2,%3}, {%4,%5,%6,%7}, {%8,%9}, {%0,%1,%2,%3};"
        : "+f"(c[0]), "+f"(c[1]), "+f"(c[2]), "+f"(c[3])
        : "r"(a[0]), "r"(a[1]), "r"(a[2]), "r"(a[3]), "r"(b0), "r"(b1));
}
// pack two fp32 -> bf16x2 (first arg in low half)
__device__ __forceinline__ uint32_t packb(float lo, float hi) {
    uint32_t r;
    asm("cvt.rn.bf16x2.f32 %0, %1, %2;" : "=r"(r) : "f"(hi), "f"(lo));
    return r;
}
__device__ __forceinline__ float ublo(uint32_t u) { return __uint_as_float(u << 16); }
__device__ __forceinline__ float ubhi(uint32_t u) { return __uint_as_float(u & 0xffff0000u); }

// FMA-pipe exp2 (no MUFU): clamps at -126.
__device__ __forceinline__ float fexp2(float x) {
    x = fmaxf(x, -126.0f);
    float fm = x + 12582912.0f;                 // 1.5 * 2^23 (rint magic)
    int ir = __float_as_int(fm) - 0x4b400000;
    float r = fm - 12582912.0f;
    float f = x - r;                            // [-0.5, 0.5]
    float p = 1.3333558146e-3f;
    p = fmaf(p, f, 9.6181291076e-3f);
    p = fmaf(p, f, 5.5504108665e-2f);
    p = fmaf(p, f, 2.4022650696e-1f);
    p = fmaf(p, f, 6.9314718056e-1f);
    p = fmaf(p, f, 1.0f);
    return __int_as_float(__float_as_int(p) + (ir << 23));
}

// ---------------------------------------------------------------------------
// Conversion kernels
// ---------------------------------------------------------------------------
__global__ __launch_bounds__(256) void split_hi_lo(const float4* __restrict__ in,
                                                   uint2* __restrict__ hi,
                                                   uint2* __restrict__ lo, int n4) {
    int i = blockIdx.x * blockDim.x + threadIdx.x;
    if (i >= n4) return;
    float4 v = in[i];
    uint32_t h0 = packb(v.x, v.y), h1 = packb(v.z, v.w);
    uint32_t l0 = packb(v.x - ublo(h0), v.y - ubhi(h0));
    uint32_t l1 = packb(v.z - ublo(h1), v.w - ubhi(h1));
    hi[i] = make_uint2(h0, h1);
    lo[i] = make_uint2(l0, l1);
}

// W [1024(K) x 1024(N)] -> Wt_hi/lo [N, K] bf16
__global__ __launch_bounds__(256) void transpose_split(const float* __restrict__ W,
                                                       __nv_bfloat16* __restrict__ Thi,
                                                       __nv_bfloat16* __restrict__ Tlo) {
    __shared__ float t[32][33];
    const int n0 = blockIdx.x * 32, k0 = blockIdx.y * 32;
    const int tx = threadIdx.x, ty = threadIdx.y;  // 32 x 8
#pragma unroll
    for (int r = ty; r < 32; r += 8)
        t[r][tx] = W[(size_t)(k0 + r) * 1024 + n0 + tx];
    __syncthreads();
#pragma unroll
    for (int r = ty; r < 32; r += 8) {
        float v = t[tx][r];
        __nv_bfloat16 h = __float2bfloat16(v);
        __nv_bfloat16 l = __float2bfloat16(v - __bfloat162float(h));
        size_t o = (size_t)(n0 + r) * 1024 + k0 + tx;
        Thi[o] = h; Tlo[o] = l;
    }
}

// ---------------------------------------------------------------------------
// mma.sync bf16x3 GEMM, 128x128 tile, BK=32, cp.async double buffer.
// MODE 0: C fp32 [M,1024].  MODE 1: bf16 hi/lo output in [b,h,c,d], scaled.
// ---------------------------------------------------------------------------
#define RSTR      80
#define MAT_BYTES (128 * RSTR)
#define STG_BYTES (4 * MAT_BYTES)
#define GEMM_SMEM (2 * STG_BYTES)
#define NCH       32

template <int MODE>
__global__ __launch_bounds__(256, 1) void gemm_mma_bf16x3(
    const __nv_bfloat16* __restrict__ Ahi, const __nv_bfloat16* __restrict__ Alo,
    const __nv_bfloat16* __restrict__ Bhi, const __nv_bfloat16* __restrict__ Blo,
    float* __restrict__ C, __nv_bfloat16* __restrict__ Ohi,
    __nv_bfloat16* __restrict__ Olo, float scale) {
    extern __shared__ char smem_raw[];
    const int tid = threadIdx.x;
    const int wid = tid >> 5, lane = tid & 31;
    const int brow = blockIdx.y * 128;
    const int bcol = blockIdx.x * 128;
    const uint32_t sbase = smem_u32(smem_raw);

    const int wm = (wid & 3) * 32;
    const int wn = (wid >> 2) * 64;

    const int l_row = tid >> 2;
    const int l_ch = tid & 3;
    auto load_stage = [&](int st, int kc) {
        const uint32_t so = sbase + st * STG_BYTES;
        const int k0 = kc * 32;
#pragma unroll
        for (int rep = 0; rep < 2; rep++) {
            const int row = rep * 64 + l_row;
            const uint32_t smoff = row * RSTR + l_ch * 16;
            const size_t ga = (size_t)(brow + row) * 1024 + k0 + l_ch * 8;
            const size_t gb = (size_t)(bcol + row) * 1024 + k0 + l_ch * 8;
            cp_async16(so + 0 * MAT_BYTES + smoff, Ahi + ga);
            cp_async16(so + 1 * MAT_BYTES + smoff, Alo + ga);
            cp_async16(so + 2 * MAT_BYTES + smoff, Bhi + gb);
            cp_async16(so + 3 * MAT_BYTES + smoff, Blo + gb);
        }
        CP_COMMIT();
    };

    float acc[2][8][4];
#pragma unroll
    for (int i = 0; i < 2; i++)
#pragma unroll
        for (int j = 0; j < 8; j++)
#pragma unroll
            for (int k = 0; k < 4; k++) acc[i][j][k] = 0.f;

    const int fr = lane & 15;
    const int fc = (lane >> 4) * 16;

    load_stage(0, 0);
    load_stage(1, 1);

    for (int c = 0; c < NCH; c++) {
        if (c < NCH - 1) asm volatile("cp.async.wait_group 1;" ::: "memory");
        else             asm volatile("cp.async.wait_group 0;" ::: "memory");
        __syncthreads();

        const uint32_t so = sbase + (c & 1) * STG_BYTES;
#pragma unroll
        for (int ks = 0; ks < 2; ks++) {
            uint32_t ah[2][4], al[2][4];
#pragma unroll
            for (int mt = 0; mt < 2; mt++) {
                const uint32_t ra = (wm + mt * 16 + fr) * RSTR + ks * 32 + fc;
                ldsm4(ah[mt], so + 0 * MAT_BYTES + ra);
                ldsm4(al[mt], so + 1 * MAT_BYTES + ra);
            }
            uint32_t bh[4][4], bl[4][4];
#pragma unroll
            for (int np = 0; np < 4; np++) {
                const uint32_t rb = (wn + np * 16 + fr) * RSTR + ks * 32 + fc;
                ldsm4(bh[np], so + 2 * MAT_BYTES + rb);
                ldsm4(bl[np], so + 3 * MAT_BYTES + rb);
            }
#pragma unroll
            for (int mt = 0; mt < 2; mt++) {
#pragma unroll
                for (int np = 0; np < 4; np++) {
                    mma16816(acc[mt][np * 2 + 0], ah[mt], bh[np][0], bh[np][2]);
                    mma16816(acc[mt][np * 2 + 0], ah[mt], bl[np][0], bl[np][2]);
                    mma16816(acc[mt][np * 2 + 0], al[mt], bh[np][0], bh[np][2]);
                    mma16816(acc[mt][np * 2 + 1], ah[mt], bh[np][1], bh[np][3]);
                    mma16816(acc[mt][np * 2 + 1], ah[mt], bl[np][1], bl[np][3]);
                    mma16816(acc[mt][np * 2 + 1], al[mt], bh[np][1], bh[np][3]);
                }
            }
        }
        __syncthreads();
        if (c + 2 < NCH) load_stage(c & 1, c + 2);
    }

#pragma unroll
    for (int mt = 0; mt < 2; mt++) {
#pragma unroll
        for (int nt = 0; nt < 8; nt++) {
            const int row = brow + wm + mt * 16 + (lane >> 2);
            const int col = bcol + wn + nt * 8 + (lane & 3) * 2;
            if (MODE == 0) {
                *(float2*)&C[(size_t)row * 1024 + col] =
                    make_float2(acc[mt][nt][0], acc[mt][nt][1]);
                *(float2*)&C[(size_t)(row + 8) * 1024 + col] =
                    make_float2(acc[mt][nt][2], acc[mt][nt][3]);
            } else {
                const int hh = col >> 6, dd = col & 63;
#pragma unroll
                for (int half = 0; half < 2; half++) {
                    const int r = row + half * 8;
                    const float v0 = acc[mt][nt][half * 2 + 0] * scale;
                    const float v1 = acc[mt][nt][half * 2 + 1] * scale;
                    const uint32_t hi = packb(v0, v1);
                    const uint32_t lo = packb(v0 - ublo(hi), v1 - ubhi(hi));
                    const int bb2 = r >> 11, cc2 = r & 2047;
                    const size_t off = (((size_t)(bb2 * HH + hh) * CC + cc2) * DD + dd);
                    *(uint32_t*)(Ohi + off) = hi;
                    *(uint32_t*)(Olo + off) = lo;
                }
            }
        }
    }
}

// ---------------------------------------------------------------------------
// Tensor-core causal flash attention, bf16x3 compensated.
// CTA: 128 q rows, 8 warps x 16 rows, 64-key tiles, double-buffered cp.async.
// Q prescaled by 0.125*log2(e); softmax in base-2; masked-block skipping.
// ---------------------------------------------------------------------------
#define ATS    144                 // bytes per smem row (64 bf16 + 16B pad)
#define ATILE  (64 * ATS)          // 9216
#define ASTAGE (4 * ATILE)         // Khi|Klo|Vhi|Vlo = 36864
#define ASMEM  (2 * ASTAGE)        // 73728

__global__ __launch_bounds__(256, 1) void attn_mma(
    const __nv_bfloat16* __restrict__ Qhi, const __nv_bfloat16* __restrict__ Qlo,
    const __nv_bfloat16* __restrict__ Khi, const __nv_bfloat16* __restrict__ Klo,
    const __nv_bfloat16* __restrict__ Vhi, const __nv_bfloat16* __restrict__ Vlo,
    __nv_bfloat16* __restrict__ Ohi, __nv_bfloat16* __restrict__ Olo) {
    extern __shared__ char smem_raw[];
    const uint32_t sb = smem_u32(smem_raw);
    const int tid = threadIdx.x, wid = tid >> 5, lane = tid & 31;
    const int qt = (gridDim.x - 1) - blockIdx.x;   // biggest tiles launch first
    const int h = blockIdx.y, b = blockIdx.z;
    const int q0 = qt * 128;
    const size_t bh = (size_t)(b * HH + h) * CC * DD;

    const int fr = lane & 15, fcb = (lane >> 4) * 16;

    // ---- Q tile into stage-0 region (hi at sb, lo at sb + 128*ATS) ----
    {
        const __nv_bfloat16* qh = Qhi + bh + (size_t)q0 * DD;
        const __nv_bfloat16* ql = Qlo + bh + (size_t)q0 * DD;
#pragma unroll
        for (int i = 0; i < 4; i++) {
            const int id = i * 256 + tid;       // 0..1023
            const int r = id >> 3, ch = id & 7;
            cp_async16(sb + r * ATS + ch * 16, qh + r * 64 + ch * 8);
            cp_async16(sb + 128 * ATS + r * ATS + ch * 16, ql + r * 64 + ch * 8);
        }
        CP_COMMIT();
        asm volatile("cp.async.wait_group 0;" ::: "memory");
        __syncthreads();
    }
    uint32_t qfh[4][4], qfl[4][4];
#pragma unroll
    for (int ks = 0; ks < 4; ks++) {
        const uint32_t a = sb + (wid * 16 + fr) * ATS + ks * 32 + fcb;
        ldsm4(qfh[ks], a);
        ldsm4(qfl[ks], a + 128 * ATS);
    }
    __syncthreads();

    float o[8][4];
#pragma unroll
    for (int j = 0; j < 8; j++)
#pragma unroll
        for (int k = 0; k < 4; k++) o[j][k] = 0.f;
    float mrow[2] = {-1e30f, -1e30f};
    float lrow[2] = {0.f, 0.f};

    const int nt = 2 * qt + 2;
    const int rowmax = q0 + wid * 16 + 15;       // warp-uniform max q row

    auto load_kv = [&](int t, int stage) {
        const uint32_t st = sb + stage * ASTAGE;
        const int k0 = t * 64;
#pragma unroll
        for (int i = 0; i < 2; i++) {
            const int id = i * 256 + tid;        // 0..511
            const int r = id >> 3, ch = id & 7;
            const size_t g = bh + (size_t)(k0 + r) * 64 + ch * 8;
            const uint32_t so = r * ATS + ch * 16;
            cp_async16(st + 0 * ATILE + so, Khi + g);
            cp_async16(st + 1 * ATILE + so, Klo + g);
            cp_async16(st + 2 * ATILE + so, Vhi + g);
            cp_async16(st + 3 * ATILE + so, Vlo + g);
        }
        CP_COMMIT();
    };

    load_kv(0, 0);
    if (nt > 1) load_kv(1, 1);

    for (int t = 0; t < nt; t++) {
        if (t + 1 < nt) asm volatile("cp.async.wait_group 1;" ::: "memory");
        else            asm volatile("cp.async.wait_group 0;" ::: "memory");
        __syncthreads();

        const uint32_t st = sb + (t & 1) * ASTAGE;
        const bool masked = (t >= 2 * qt);
        const int k0g = t * 64;                  // global first key of tile
        const bool skip_all = masked && (k0g > rowmax);

        if (!skip_all) {
            float s[8][4];
#pragma unroll
            for (int j = 0; j < 8; j++)
#pragma unroll
                for (int k = 0; k < 4; k++) s[j][k] = 0.f;

            // ---- S = Q @ K^T (x3 compensated), skipping fully-masked blocks ----
#pragma unroll
            for (int np = 0; np < 4; np++) {
                if (masked && (k0g + np * 16 > rowmax)) continue;
#pragma unroll
                for (int ks = 0; ks < 4; ks++) {
                    const uint32_t addr = st + (np * 16 + fr) * ATS + ks * 32 + fcb;
                    uint32_t kh[4], kl[4];
                    ldsm4(kh, addr);
                    ldsm4(kl, addr + ATILE);
                    mma16816(s[np * 2 + 0], qfh[ks], kh[0], kh[2]);
                    mma16816(s[np * 2 + 0], qfh[ks], kl[0], kl[2]);
                    mma16816(s[np * 2 + 0], qfl[ks], kh[0], kh[2]);
                    mma16816(s[np * 2 + 1], qfh[ks], kh[1], kh[3]);
                    mma16816(s[np * 2 + 1], qfh[ks], kl[1], kl[3]);
                    mma16816(s[np * 2 + 1], qfl[ks], kh[1], kh[3]);
                }
            }

            const int row0 = q0 + wid * 16 + (lane >> 2);
            if (masked) {
                const int kc0 = k0g + (lane & 3) * 2;
#pragma unroll
                for (int np8 = 0; np8 < 8; np8++) {
                    const int kc = kc0 + np8 * 8;
                    if (kc > row0)         s[np8][0] = -1e30f;
                    if (kc + 1 > row0)     s[np8][1] = -1e30f;
                    if (kc > row0 + 8)     s[np8][2] = -1e30f;
                    if (kc + 1 > row0 + 8) s[np8][3] = -1e30f;
                }
            }

            // ---- online softmax (base-2 domain) ----
            float mx0 = -1e30f, mx1 = -1e30f;
#pragma unroll
            for (int j = 0; j < 8; j++) {
                mx0 = fmaxf(mx0, fmaxf(s[j][0], s[j][1]));
                mx1 = fmaxf(mx1, fmaxf(s[j][2], s[j][3]));
            }
            mx0 = fmaxf(mx0, __shfl_xor_sync(0xffffffffu, mx0, 1));
            mx0 = fmaxf(mx0, __shfl_xor_sync(0xffffffffu, mx0, 2));
            mx1 = fmaxf(mx1, __shfl_xor_sync(0xffffffffu, mx1, 1));
            mx1 = fmaxf(mx1, __shfl_xor_sync(0xffffffffu, mx1, 2));
            const float mn0 = fmaxf(mrow[0], mx0);
            const float mn1 = fmaxf(mrow[1], mx1);
            const float al0 = fexp2(mrow[0] - mn0);
            const float al1 = fexp2(mrow[1] - mn1);
            mrow[0] = mn0;
            mrow[1] = mn1;

            float sum0 = 0.f, sum1 = 0.f;
#pragma unroll
            for (int j = 0; j < 8; j++) {
                s[j][0] = fexp2(s[j][0] - mn0);
                s[j][1] = fexp2(s[j][1] - mn0);
                s[j][2] = fexp2(s[j][2] - mn1);
                s[j][3] = fexp2(s[j][3] - mn1);
                sum0 += s[j][0] + s[j][1];
                sum1 += s[j][2] + s[j][3];
            }
            sum0 += __shfl_xor_sync(0xffffffffu, sum0, 1);
            sum0 += __shfl_xor_sync(0xffffffffu, sum0, 2);
            sum1 += __shfl_xor_sync(0xffffffffu, sum1, 1);
            sum1 += __shfl_xor_sync(0xffffffffu, sum1, 2);
            lrow[0] = lrow[0] * al0 + sum0;
            lrow[1] = lrow[1] * al1 + sum1;
#pragma unroll
            for (int j = 0; j < 8; j++) {
                o[j][0] *= al0; o[j][1] *= al0;
                o[j][2] *= al1; o[j][3] *= al1;
            }

            // ---- pack P hi/lo into A-fragments ----
            uint32_t pfh[4][4], pfl[4][4];
#pragma unroll
            for (int ks = 0; ks < 4; ks++) {
                const int e = 2 * ks, d = 2 * ks + 1;
                pfh[ks][0] = packb(s[e][0], s[e][1]);
                pfh[ks][1] = packb(s[e][2], s[e][3]);
                pfh[ks][2] = packb(s[d][0], s[d][1]);
                pfh[ks][3] = packb(s[d][2], s[d][3]);
                pfl[ks][0] = packb(s[e][0] - ublo(pfh[ks][0]), s[e][1] - ubhi(pfh[ks][0]));
                pfl[ks][1] = packb(s[e][2] - ublo(pfh[ks][1]), s[e][3] - ubhi(pfh[ks][1]));
                pfl[ks][2] = packb(s[d][0] - ublo(pfh[ks][2]), s[d][1] - ubhi(pfh[ks][2]));
                pfl[ks][3] = packb(s[d][2] - ublo(pfh[ks][3]), s[d][3] - ubhi(pfh[ks][3]));
            }

            // ---- O += P @ V (x3), V via ldmatrix.trans, skip masked key blocks ----
#pragma unroll
            for (int ks = 0; ks < 4; ks++) {
                if (masked && (k0g + ks * 16 > rowmax)) continue;
#pragma unroll
                for (int np = 0; np < 4; np++) {
                    const uint32_t addr =
                        st + 2 * ATILE + (ks * 16 + fr) * ATS + np * 32 + fcb;
                    uint32_t vh[4], vl[4];
                    ldsm4t(vh, addr);
                    ldsm4t(vl, addr + ATILE);
                    mma16816(o[np * 2 + 0], pfh[ks], vh[0], vh[1]);
                    mma16816(o[np * 2 + 0], pfh[ks], vl[0], vl[1]);
                    mma16816(o[np * 2 + 0], pfl[ks], vh[0], vh[1]);
                    mma16816(o[np * 2 + 1], pfh[ks], vh[2], vh[3]);
                    mma16816(o[np * 2 + 1], pfh[ks], vl[2], vl[3]);
                    mma16816(o[np * 2 + 1], pfl[ks], vh[2], vh[3]);
                }
            }
        }
        __syncthreads();
        if (t + 2 < nt) load_kv(t + 2, t & 1);
    }

    // ---- epilogue: normalize, split hi/lo, store to [token, h*64+d] ----
    const float inv0 = 1.0f / lrow[0];
    const float inv1 = 1.0f / lrow[1];
    const int row = q0 + wid * 16 + (lane >> 2);
#pragma unroll
    for (int np8 = 0; np8 < 8; np8++) {
        const int col = np8 * 8 + (lane & 3) * 2;
        const size_t off0 = (size_t)(b * CC + row) * HDIM + h * 64 + col;
        const size_t off8 = off0 + (size_t)8 * HDIM;
        float v0 = o[np8][0] * inv0, v1 = o[np8][1] * inv0;
        float v2 = o[np8][2] * inv1, v3 = o[np8][3] * inv1;
        uint32_t hi0 = packb(v0, v1);
        uint32_t lo0 = packb(v0 - ublo(hi0), v1 - ubhi(hi0));
        uint32_t hi8 = packb(v2, v3);
        uint32_t lo8 = packb(v2 - ublo(hi8), v3 - ubhi(hi8));
        *(uint32_t*)(Ohi + off0) = hi0;
        *(uint32_t*)(Olo + off0) = lo0;
        *(uint32_t*)(Ohi + off8) = hi8;
        *(uint32_t*)(Olo + off8) = lo8;
    }
}

// ---------------------------------------------------------------------------
extern "C" void kernel_launch(void* const* d_in, const int* in_sizes, int n_in,
                              void* d_out, int out_size) {
    const float* x  = (const float*)d_in[0];
    const float* Wq = (const float*)d_in[1];
    const float* Wk = (const float*)d_in[2];
    const float* Wv = (const float*)d_in[3];
    const float* Wo = (const float*)d_in[4];
    float* out = (float*)d_out;

    __nv_bfloat16 *xhi, *xlo, *hhi, *hlo, *wthi, *wtlo;
    __nv_bfloat16 *Qhi, *Qlo, *Khi, *Klo, *Vhi, *Vlo;
    cudaGetSymbolAddress((void**)&xhi, g_xhi);
    cudaGetSymbolAddress((void**)&xlo, g_xlo);
    cudaGetSymbolAddress((void**)&hhi, g_hhi);
    cudaGetSymbolAddress((void**)&hlo, g_hlo);
    cudaGetSymbolAddress((void**)&wthi, g_wthi);
    cudaGetSymbolAddress((void**)&wtlo, g_wtlo);
    cudaGetSymbolAddress((void**)&Qhi, g_Qhi);
    cudaGetSymbolAddress((void**)&Qlo, g_Qlo);
    cudaGetSymbolAddress((void**)&Khi, g_Khi);
    cudaGetSymbolAddress((void**)&Klo, g_Klo);
    cudaGetSymbolAddress((void**)&Vhi, g_Vhi);
    cudaGetSymbolAddress((void**)&Vlo, g_Vlo);

    static bool attr_set = false;
    if (!attr_set) {
        cudaFuncSetAttribute(gemm_mma_bf16x3<0>,
                             cudaFuncAttributeMaxDynamicSharedMemorySize, GEMM_SMEM);
        cudaFuncSetAttribute(gemm_mma_bf16x3<1>,
                             cudaFuncAttributeMaxDynamicSharedMemorySize, GEMM_SMEM);
        cudaFuncSetAttribute(attn_mma,
                             cudaFuncAttributeMaxDynamicSharedMemorySize, ASMEM);
        attr_set = true;
    }

    // 1) split x into bf16 hi/lo
    {
        int n4 = MM * EE / 4;
        split_hi_lo<<<(n4 + 255) / 256, 256>>>((const float4*)x, (uint2*)xhi, (uint2*)xlo, n4);
    }
    // 2) transpose+split all weights
    const float* Ws[4] = {Wq, Wk, Wv, Wo};
    for (int i = 0; i < 4; i++)
        transpose_split<<<dim3(32, 32), dim3(32, 8)>>>(Ws[i], wthi + (size_t)i * EE * HDIM,
                                                       wtlo + (size_t)i * EE * HDIM);
    // 3) projections -> bf16 hi/lo in [b,h,c,d]; Q prescaled by 0.125*log2(e)
    dim3 ggrid(HDIM / 128, MM / 128);
    const float qscale = 0.125f * 1.4426950408889634f;
    gemm_mma_bf16x3<1><<<ggrid, 256, GEMM_SMEM>>>(
        xhi, xlo, wthi + 0 * (size_t)EE * HDIM, wtlo + 0 * (size_t)EE * HDIM,
        nullptr, Qhi, Qlo, qscale);
    gemm_mma_bf16x3<1><<<ggrid, 256, GEMM_SMEM>>>(
        xhi, xlo, wthi + 1 * (size_t)EE * HDIM, wtlo + 1 * (size_t)EE * HDIM,
        nullptr, Khi, Klo, 1.0f);
    gemm_mma_bf16x3<1><<<ggrid, 256, GEMM_SMEM>>>(
        xhi, xlo, wthi + 2 * (size_t)EE * HDIM, wtlo + 2 * (size_t)EE * HDIM,
        nullptr, Vhi, Vlo, 1.0f);

    // 4) attention -> hidden bf16 hi/lo [token, hdim]
    attn_mma<<<dim3(CC / 128, HH, BB), 256, ASMEM>>>(Qhi, Qlo, Khi, Klo, Vhi, Vlo, hhi, hlo);

    // 5) output projection -> fp32 out
    gemm_mma_bf16x3<0><<<ggrid, 256, GEMM_SMEM>>>(
        hhi, hlo, wthi + 3 * (size_t)EE * HDIM, wtlo + 3 * (size_t)EE * HDIM,
        out, nullptr, nullptr, 1.0f);
}

// round 6
// speedup vs baseline: 1.0050x; 1.0050x over previous
#include <cuda_runtime.h>
#include <cuda_bf16.h>
#include <cstdint>

// Problem constants
#define BB   4
#define CC   2048
#define EE   1024
#define HH   16
#define DD   64
#define HDIM 1024
#define MM   (BB*CC)        // 8192

// ---------------- scratch (device globals; no allocs allowed) ----------------
__device__ __nv_bfloat16 g_xhi[MM * EE];
__device__ __nv_bfloat16 g_xlo[MM * EE];
__device__ __nv_bfloat16 g_hhi[MM * HDIM];
__device__ __nv_bfloat16 g_hlo[MM * HDIM];
__device__ __nv_bfloat16 g_wthi[4][EE * HDIM];   // transposed weights [N,K] bf16 hi
__device__ __nv_bfloat16 g_wtlo[4][EE * HDIM];   // transposed weights [N,K] bf16 lo
// Q/K/V in [b, h, c, d] layout, bf16 hi/lo
__device__ __nv_bfloat16 g_Qhi[MM * HDIM];
__device__ __nv_bfloat16 g_Qlo[MM * HDIM];
__device__ __nv_bfloat16 g_Khi[MM * HDIM];
__device__ __nv_bfloat16 g_Klo[MM * HDIM];
__device__ __nv_bfloat16 g_Vhi[MM * HDIM];
__device__ __nv_bfloat16 g_Vlo[MM * HDIM];

// ---------------- helpers ----------------
__device__ __forceinline__ uint32_t smem_u32(const void* p) {
    uint32_t a;
    asm("{ .reg .u64 t; cvta.to.shared.u64 t, %1; cvt.u32.u64 %0, t; }" : "=r"(a) : "l"(p));
    return a;
}
__device__ __forceinline__ void cp_async16(uint32_t saddr, const void* gaddr) {
    asm volatile("cp.async.cg.shared.global [%0], [%1], 16;" :: "r"(saddr), "l"(gaddr));
}
#define CP_COMMIT() asm volatile("cp.async.commit_group;" ::: "memory")

__device__ __forceinline__ void ldsm4(uint32_t r[4], uint32_t addr) {
    asm volatile("ldmatrix.sync.aligned.m8n8.x4.shared.b16 {%0,%1,%2,%3}, [%4];"
                 : "=r"(r[0]), "=r"(r[1]), "=r"(r[2]), "=r"(r[3]) : "r"(addr));
}
__device__ __forceinline__ void ldsm4t(uint32_t r[4], uint32_t addr) {
    asm volatile("ldmatrix.sync.aligned.m8n8.x4.trans.shared.b16 {%0,%1,%2,%3}, [%4];"
                 : "=r"(r[0]), "=r"(r[1]), "=r"(r[2]), "=r"(r[3]) : "r"(addr));
}
__device__ __forceinline__ void mma16816(float c[4], const uint32_t a[4],
                                         uint32_t b0, uint32_t b1) {
    asm volatile(
        "mma.sync.aligned.m16n8k16.row.col.f32.bf16.bf16.f32 "
        "{%0,%1,%2,%3}, {%4,%5,%6,%7}, {%8,%9}, {%0,%1,%2,%3};"
        : "+f"(c[0]), "+f"(c[1]), "+f"(c[2]), "+f"(c[3])
        : "r"(a[0]), "r"(a[1]), "r"(a[2]), "r"(a[3]), "r"(b0), "r"(b1));
}
// pack two fp32 -> bf16x2 (first arg in low half)
__device__ __forceinline__ uint32_t packb(float lo, float hi) {
    uint32_t r;
    asm("cvt.rn.bf16x2.f32 %0, %1, %2;" : "=r"(r) : "f"(hi), "f"(lo));
    return r;
}
__device__ __forceinline__ float ublo(uint32_t u) { return __uint_as_float(u << 16); }
__device__ __forceinline__ float ubhi(uint32_t u) { return __uint_as_float(u & 0xffff0000u); }

// FMA-pipe exp2 (no MUFU): clamps at -126.
__device__ __forceinline__ float fexp2(float x) {
    x = fmaxf(x, -126.0f);
    float fm = x + 12582912.0f;                 // 1.5 * 2^23 (rint magic)
    int ir = __float_as_int(fm) - 0x4b400000;
    float r = fm - 12582912.0f;
    float f = x - r;                            // [-0.5, 0.5]
    float p = 1.3333558146e-3f;
    p = fmaf(p, f, 9.6181291076e-3f);
    p = fmaf(p, f, 5.5504108665e-2f);
    p = fmaf(p, f, 2.4022650696e-1f);
    p = fmaf(p, f, 6.9314718056e-1f);
    p = fmaf(p, f, 1.0f);
    return __int_as_float(__float_as_int(p) + (ir << 23));
}

// ---------------------------------------------------------------------------
// Conversion kernels
// ---------------------------------------------------------------------------
__global__ __launch_bounds__(256) void split_hi_lo(const float4* __restrict__ in,
                                                   uint2* __restrict__ hi,
                                                   uint2* __restrict__ lo, int n4) {
    int i = blockIdx.x * blockDim.x + threadIdx.x;
    if (i >= n4) return;
    float4 v = in[i];
    uint32_t h0 = packb(v.x, v.y), h1 = packb(v.z, v.w);
    uint32_t l0 = packb(v.x - ublo(h0), v.y - ubhi(h0));
    uint32_t l1 = packb(v.z - ublo(h1), v.w - ubhi(h1));
    hi[i] = make_uint2(h0, h1);
    lo[i] = make_uint2(l0, l1);
}

// W [1024(K) x 1024(N)] -> Wt_hi/lo [N, K] bf16
__global__ __launch_bounds__(256) void transpose_split(const float* __restrict__ W,
                                                       __nv_bfloat16* __restrict__ Thi,
                                                       __nv_bfloat16* __restrict__ Tlo) {
    __shared__ float t[32][33];
    const int n0 = blockIdx.x * 32, k0 = blockIdx.y * 32;
    const int tx = threadIdx.x, ty = threadIdx.y;  // 32 x 8
#pragma unroll
    for (int r = ty; r < 32; r += 8)
        t[r][tx] = W[(size_t)(k0 + r) * 1024 + n0 + tx];
    __syncthreads();
#pragma unroll
    for (int r = ty; r < 32; r += 8) {
        float v = t[tx][r];
        __nv_bfloat16 h = __float2bfloat16(v);
        __nv_bfloat16 l = __float2bfloat16(v - __bfloat162float(h));
        size_t o = (size_t)(n0 + r) * 1024 + k0 + tx;
        Thi[o] = h; Tlo[o] = l;
    }
}

// ---------------------------------------------------------------------------
// mma.sync bf16x3 GEMM, 128x128 tile, BK=32, cp.async double buffer.
// MODE 0: C fp32 [M,1024].  MODE 1: bf16 hi/lo output in [b,h,c,d], scaled.
// ---------------------------------------------------------------------------
#define RSTR      80
#define MAT_BYTES (128 * RSTR)
#define STG_BYTES (4 * MAT_BYTES)
#define GEMM_SMEM (2 * STG_BYTES)
#define NCH       32

template <int MODE>
__global__ __launch_bounds__(256, 1) void gemm_mma_bf16x3(
    const __nv_bfloat16* __restrict__ Ahi, const __nv_bfloat16* __restrict__ Alo,
    const __nv_bfloat16* __restrict__ Bhi, const __nv_bfloat16* __restrict__ Blo,
    float* __restrict__ C, __nv_bfloat16* __restrict__ Ohi,
    __nv_bfloat16* __restrict__ Olo, float scale) {
    extern __shared__ char smem_raw[];
    const int tid = threadIdx.x;
    const int wid = tid >> 5, lane = tid & 31;
    const int brow = blockIdx.y * 128;
    const int bcol = blockIdx.x * 128;
    const uint32_t sbase = smem_u32(smem_raw);

    const int wm = (wid & 3) * 32;
    const int wn = (wid >> 2) * 64;

    const int l_row = tid >> 2;
    const int l_ch = tid & 3;
    auto load_stage = [&](int st, int kc) {
        const uint32_t so = sbase + st * STG_BYTES;
        const int k0 = kc * 32;
#pragma unroll
        for (int rep = 0; rep < 2; rep++) {
            const int row = rep * 64 + l_row;
            const uint32_t smoff = row * RSTR + l_ch * 16;
            const size_t ga = (size_t)(brow + row) * 1024 + k0 + l_ch * 8;
            const size_t gb = (size_t)(bcol + row) * 1024 + k0 + l_ch * 8;
            cp_async16(so + 0 * MAT_BYTES + smoff, Ahi + ga);
            cp_async16(so + 1 * MAT_BYTES + smoff, Alo + ga);
            cp_async16(so + 2 * MAT_BYTES + smoff, Bhi + gb);
            cp_async16(so + 3 * MAT_BYTES + smoff, Blo + gb);
        }
        CP_COMMIT();
    };

    float acc[2][8][4];
#pragma unroll
    for (int i = 0; i < 2; i++)
#pragma unroll
        for (int j = 0; j < 8; j++)
#pragma unroll
            for (int k = 0; k < 4; k++) acc[i][j][k] = 0.f;

    const int fr = lane & 15;
    const int fc = (lane >> 4) * 16;

    load_stage(0, 0);
    load_stage(1, 1);

    for (int c = 0; c < NCH; c++) {
        if (c < NCH - 1) asm volatile("cp.async.wait_group 1;" ::: "memory");
        else             asm volatile("cp.async.wait_group 0;" ::: "memory");
        __syncthreads();

        const uint32_t so = sbase + (c & 1) * STG_BYTES;
#pragma unroll
        for (int ks = 0; ks < 2; ks++) {
            uint32_t ah[2][4], al[2][4];
#pragma unroll
            for (int mt = 0; mt < 2; mt++) {
                const uint32_t ra = (wm + mt * 16 + fr) * RSTR + ks * 32 + fc;
                ldsm4(ah[mt], so + 0 * MAT_BYTES + ra);
                ldsm4(al[mt], so + 1 * MAT_BYTES + ra);
            }
            uint32_t bh[4][4], bl[4][4];
#pragma unroll
            for (int np = 0; np < 4; np++) {
                const uint32_t rb = (wn + np * 16 + fr) * RSTR + ks * 32 + fc;
                ldsm4(bh[np], so + 2 * MAT_BYTES + rb);
                ldsm4(bl[np], so + 3 * MAT_BYTES + rb);
            }
#pragma unroll
            for (int mt = 0; mt < 2; mt++) {
#pragma unroll
                for (int np = 0; np < 4; np++) {
                    mma16816(acc[mt][np * 2 + 0], ah[mt], bh[np][0], bh[np][2]);
                    mma16816(acc[mt][np * 2 + 0], ah[mt], bl[np][0], bl[np][2]);
                    mma16816(acc[mt][np * 2 + 0], al[mt], bh[np][0], bh[np][2]);
                    mma16816(acc[mt][np * 2 + 1], ah[mt], bh[np][1], bh[np][3]);
                    mma16816(acc[mt][np * 2 + 1], ah[mt], bl[np][1], bl[np][3]);
                    mma16816(acc[mt][np * 2 + 1], al[mt], bh[np][1], bh[np][3]);
                }
            }
        }
        __syncthreads();
        if (c + 2 < NCH) load_stage(c & 1, c + 2);
    }

#pragma unroll
    for (int mt = 0; mt < 2; mt++) {
#pragma unroll
        for (int nt = 0; nt < 8; nt++) {
            const int row = brow + wm + mt * 16 + (lane >> 2);
            const int col = bcol + wn + nt * 8 + (lane & 3) * 2;
            if (MODE == 0) {
                *(float2*)&C[(size_t)row * 1024 + col] =
                    make_float2(acc[mt][nt][0], acc[mt][nt][1]);
                *(float2*)&C[(size_t)(row + 8) * 1024 + col] =
                    make_float2(acc[mt][nt][2], acc[mt][nt][3]);
            } else {
                const int hh = col >> 6, dd = col & 63;
#pragma unroll
                for (int half = 0; half < 2; half++) {
                    const int r = row + half * 8;
                    const float v0 = acc[mt][nt][half * 2 + 0] * scale;
                    const float v1 = acc[mt][nt][half * 2 + 1] * scale;
                    const uint32_t hi = packb(v0, v1);
                    const uint32_t lo = packb(v0 - ublo(hi), v1 - ubhi(hi));
                    const int bb2 = r >> 11, cc2 = r & 2047;
                    const size_t off = (((size_t)(bb2 * HH + hh) * CC + cc2) * DD + dd);
                    *(uint32_t*)(Ohi + off) = hi;
                    *(uint32_t*)(Olo + off) = lo;
                }
            }
        }
    }
}

// ---------------------------------------------------------------------------
// Tensor-core causal flash attention, bf16x3 compensated.
// CTA: 64 q rows, 4 warps x 16 rows, 128 threads, 2 CTAs/SM for overlap.
// 64-key tiles double-buffered via cp.async. Q prescaled by 0.125*log2(e);
// softmax in base-2; warp-uniform masked-block skipping.
// ---------------------------------------------------------------------------
#define ATS    144                 // bytes per smem row (64 bf16 + 16B pad)
#define ATILE  (64 * ATS)          // 9216
#define ASTAGE (4 * ATILE)         // Khi|Klo|Vhi|Vlo = 36864
#define ASMEM  (2 * ASTAGE)        // 73728

__global__ __launch_bounds__(128, 2) void attn_mma(
    const __nv_bfloat16* __restrict__ Qhi, const __nv_bfloat16* __restrict__ Qlo,
    const __nv_bfloat16* __restrict__ Khi, const __nv_bfloat16* __restrict__ Klo,
    const __nv_bfloat16* __restrict__ Vhi, const __nv_bfloat16* __restrict__ Vlo,
    __nv_bfloat16* __restrict__ Ohi, __nv_bfloat16* __restrict__ Olo) {
    extern __shared__ char smem_raw[];
    const uint32_t sb = smem_u32(smem_raw);
    const int tid = threadIdx.x, wid = tid >> 5, lane = tid & 31;
    const int qt = (gridDim.x - 1) - blockIdx.x;   // biggest tiles launch first
    const int h = blockIdx.y, b = blockIdx.z;
    const int q0 = qt * 64;
    const size_t bh = (size_t)(b * HH + h) * CC * DD;

    const int fr = lane & 15, fcb = (lane >> 4) * 16;

    // ---- Q tile (64 rows) into stage-0 region (hi at sb, lo at sb + 64*ATS) ----
    {
        const __nv_bfloat16* qh = Qhi + bh + (size_t)q0 * DD;
        const __nv_bfloat16* ql = Qlo + bh + (size_t)q0 * DD;
#pragma unroll
        for (int i = 0; i < 4; i++) {
            const int id = i * 128 + tid;       // 0..511
            const int r = id >> 3, ch = id & 7;
            cp_async16(sb + r * ATS + ch * 16, qh + r * 64 + ch * 8);
            cp_async16(sb + 64 * ATS + r * ATS + ch * 16, ql + r * 64 + ch * 8);
        }
        CP_COMMIT();
        asm volatile("cp.async.wait_group 0;" ::: "memory");
        __syncthreads();
    }
    uint32_t qfh[4][4], qfl[4][4];
#pragma unroll
    for (int ks = 0; ks < 4; ks++) {
        const uint32_t a = sb + (wid * 16 + fr) * ATS + ks * 32 + fcb;
        ldsm4(qfh[ks], a);
        ldsm4(qfl[ks], a + 64 * ATS);
    }
    __syncthreads();

    float o[8][4];
#pragma unroll
    for (int j = 0; j < 8; j++)
#pragma unroll
        for (int k = 0; k < 4; k++) o[j][k] = 0.f;
    float mrow[2] = {-1e30f, -1e30f};
    float lrow[2] = {0.f, 0.f};

    const int nt = qt + 1;                       // keys 0 .. q0+63
    const int rowmax = q0 + wid * 16 + 15;       // warp-uniform max q row

    auto load_kv = [&](int t, int stage) {
        const uint32_t st = sb + stage * ASTAGE;
        const int k0 = t * 64;
#pragma unroll
        for (int i = 0; i < 4; i++) {
            const int id = i * 128 + tid;        // 0..511
            const int r = id >> 3, ch = id & 7;
            const size_t g = bh + (size_t)(k0 + r) * 64 + ch * 8;
            const uint32_t so = r * ATS + ch * 16;
            cp_async16(st + 0 * ATILE + so, Khi + g);
            cp_async16(st + 1 * ATILE + so, Klo + g);
            cp_async16(st + 2 * ATILE + so, Vhi + g);
            cp_async16(st + 3 * ATILE + so, Vlo + g);
        }
        CP_COMMIT();
    };

    load_kv(0, 0);
    if (nt > 1) load_kv(1, 1);

    for (int t = 0; t < nt; t++) {
        if (t + 1 < nt) asm volatile("cp.async.wait_group 1;" ::: "memory");
        else            asm volatile("cp.async.wait_group 0;" ::: "memory");
        __syncthreads();

        const uint32_t st = sb + (t & 1) * ASTAGE;
        const bool masked = (t == qt);
        const int k0g = t * 64;                  // global first key of tile

        {
            float s[8][4];
#pragma unroll
            for (int j = 0; j < 8; j++)
#pragma unroll
                for (int k = 0; k < 4; k++) s[j][k] = 0.f;

            // ---- S = Q @ K^T (x3 compensated), skipping fully-masked blocks ----
#pragma unroll
            for (int np = 0; np < 4; np++) {
                if (masked && (k0g + np * 16 > rowmax)) continue;
#pragma unroll
                for (int ks = 0; ks < 4; ks++) {
                    const uint32_t addr = st + (np * 16 + fr) * ATS + ks * 32 + fcb;
                    uint32_t kh[4], kl[4];
                    ldsm4(kh, addr);
                    ldsm4(kl, addr + ATILE);
                    mma16816(s[np * 2 + 0], qfh[ks], kh[0], kh[2]);
                    mma16816(s[np * 2 + 0], qfh[ks], kl[0], kl[2]);
                    mma16816(s[np * 2 + 0], qfl[ks], kh[0], kh[2]);
                    mma16816(s[np * 2 + 1], qfh[ks], kh[1], kh[3]);
                    mma16816(s[np * 2 + 1], qfh[ks], kl[1], kl[3]);
                    mma16816(s[np * 2 + 1], qfl[ks], kh[1], kh[3]);
                }
            }

            const int row0 = q0 + wid * 16 + (lane >> 2);
            if (masked) {
                const int kc0 = k0g + (lane & 3) * 2;
#pragma unroll
                for (int np8 = 0; np8 < 8; np8++) {
                    const int kc = kc0 + np8 * 8;
                    if (kc > row0)         s[np8][0] = -1e30f;
                    if (kc + 1 > row0)     s[np8][1] = -1e30f;
                    if (kc > row0 + 8)     s[np8][2] = -1e30f;
                    if (kc + 1 > row0 + 8) s[np8][3] = -1e30f;
                }
            }

            // ---- online softmax (base-2 domain) ----
            float mx0 = -1e30f, mx1 = -1e30f;
#pragma unroll
            for (int j = 0; j < 8; j++) {
                mx0 = fmaxf(mx0, fmaxf(s[j][0], s[j][1]));
                mx1 = fmaxf(mx1, fmaxf(s[j][2], s[j][3]));
            }
            mx0 = fmaxf(mx0, __shfl_xor_sync(0xffffffffu, mx0, 1));
            mx0 = fmaxf(mx0, __shfl_xor_sync(0xffffffffu, mx0, 2));
            mx1 = fmaxf(mx1, __shfl_xor_sync(0xffffffffu, mx1, 1));
            mx1 = fmaxf(mx1, __shfl_xor_sync(0xffffffffu, mx1, 2));
            const float mn0 = fmaxf(mrow[0], mx0);
            const float mn1 = fmaxf(mrow[1], mx1);
            const float al0 = fexp2(mrow[0] - mn0);
            const float al1 = fexp2(mrow[1] - mn1);
            mrow[0] = mn0;
            mrow[1] = mn1;

            float sum0 = 0.f, sum1 = 0.f;
#pragma unroll
            for (int j = 0; j < 8; j++) {
                s[j][0] = fexp2(s[j][0] - mn0);
                s[j][1] = fexp2(s[j][1] - mn0);
                s[j][2] = fexp2(s[j][2] - mn1);
                s[j][3] = fexp2(s[j][3] - mn1);
                sum0 += s[j][0] + s[j][1];
                sum1 += s[j][2] + s[j][3];
            }
            sum0 += __shfl_xor_sync(0xffffffffu, sum0, 1);
            sum0 += __shfl_xor_sync(0xffffffffu, sum0, 2);
            sum1 += __shfl_xor_sync(0xffffffffu, sum1, 1);
            sum1 += __shfl_xor_sync(0xffffffffu, sum1, 2);
            lrow[0] = lrow[0] * al0 + sum0;
            lrow[1] = lrow[1] * al1 + sum1;
#pragma unroll
            for (int j = 0; j < 8; j++) {
                o[j][0] *= al0; o[j][1] *= al0;
                o[j][2] *= al1; o[j][3] *= al1;
            }

            // ---- pack P hi/lo into A-fragments ----
            uint32_t pfh[4][4], pfl[4][4];
#pragma unroll
            for (int ks = 0; ks < 4; ks++) {
                const int e = 2 * ks, d = 2 * ks + 1;
                pfh[ks][0] = packb(s[e][0], s[e][1]);
                pfh[ks][1] = packb(s[e][2], s[e][3]);
                pfh[ks][2] = packb(s[d][0], s[d][1]);
                pfh[ks][3] = packb(s[d][2], s[d][3]);
                pfl[ks][0] = packb(s[e][0] - ublo(pfh[ks][0]), s[e][1] - ubhi(pfh[ks][0]));
                pfl[ks][1] = packb(s[e][2] - ublo(pfh[ks][1]), s[e][3] - ubhi(pfh[ks][1]));
                pfl[ks][2] = packb(s[d][0] - ublo(pfh[ks][2]), s[d][1] - ubhi(pfh[ks][2]));
                pfl[ks][3] = packb(s[d][2] - ublo(pfh[ks][3]), s[d][3] - ubhi(pfh[ks][3]));
            }

            // ---- O += P @ V (x3), V via ldmatrix.trans, skip masked key blocks ----
#pragma unroll
            for (int ks = 0; ks < 4; ks++) {
                if (masked && (k0g + ks * 16 > rowmax)) continue;
#pragma unroll
                for (int np = 0; np < 4; np++) {
                    const uint32_t addr =
                        st + 2 * ATILE + (ks * 16 + fr) * ATS + np * 32 + fcb;
                    uint32_t vh[4], vl[4];
                    ldsm4t(vh, addr);
                    ldsm4t(vl, addr + ATILE);
                    mma16816(o[np * 2 + 0], pfh[ks], vh[0], vh[1]);
                    mma16816(o[np * 2 + 0], pfh[ks], vl[0], vl[1]);
                    mma16816(o[np * 2 + 0], pfl[ks], vh[0], vh[1]);
                    mma16816(o[np * 2 + 1], pfh[ks], vh[2], vh[3]);
                    mma16816(o[np * 2 + 1], pfh[ks], vl[2], vl[3]);
                    mma16816(o[np * 2 + 1], pfl[ks], vh[2], vh[3]);
                }
            }
        }
        __syncthreads();
        if (t + 2 < nt) load_kv(t + 2, t & 1);
    }

    // ---- epilogue: normalize, split hi/lo, store to [token, h*64+d] ----
    const float inv0 = 1.0f / lrow[0];
    const float inv1 = 1.0f / lrow[1];
    const int row = q0 + wid * 16 + (lane >> 2);
#pragma unroll
    for (int np8 = 0; np8 < 8; np8++) {
        const int col = np8 * 8 + (lane & 3) * 2;
        const size_t off0 = (size_t)(b * CC + row) * HDIM + h * 64 + col;
        const size_t off8 = off0 + (size_t)8 * HDIM;
        float v0 = o[np8][0] * inv0, v1 = o[np8][1] * inv0;
        float v2 = o[np8][2] * inv1, v3 = o[np8][3] * inv1;
        uint32_t hi0 = packb(v0, v1);
        uint32_t lo0 = packb(v0 - ublo(hi0), v1 - ubhi(hi0));
        uint32_t hi8 = packb(v2, v3);
        uint32_t lo8 = packb(v2 - ublo(hi8), v3 - ubhi(hi8));
        *(uint32_t*)(Ohi + off0) = hi0;
        *(uint32_t*)(Olo + off0) = lo0;
        *(uint32_t*)(Ohi + off8) = hi8;
        *(uint32_t*)(Olo + off8) = lo8;
    }
}

// ---------------------------------------------------------------------------
extern "C" void kernel_launch(void* const* d_in, const int* in_sizes, int n_in,
                              void* d_out, int out_size) {
    const float* x  = (const float*)d_in[0];
    const float* Wq = (const float*)d_in[1];
    const float* Wk = (const float*)d_in[2];
    const float* Wv = (const float*)d_in[3];
    const float* Wo = (const float*)d_in[4];
    float* out = (float*)d_out;

    __nv_bfloat16 *xhi, *xlo, *hhi, *hlo, *wthi, *wtlo;
    __nv_bfloat16 *Qhi, *Qlo, *Khi, *Klo, *Vhi, *Vlo;
    cudaGetSymbolAddress((void**)&xhi, g_xhi);
    cudaGetSymbolAddress((void**)&xlo, g_xlo);
    cudaGetSymbolAddress((void**)&hhi, g_hhi);
    cudaGetSymbolAddress((void**)&hlo, g_hlo);
    cudaGetSymbolAddress((void**)&wthi, g_wthi);
    cudaGetSymbolAddress((void**)&wtlo, g_wtlo);
    cudaGetSymbolAddress((void**)&Qhi, g_Qhi);
    cudaGetSymbolAddress((void**)&Qlo, g_Qlo);
    cudaGetSymbolAddress((void**)&Khi, g_Khi);
    cudaGetSymbolAddress((void**)&Klo, g_Klo);
    cudaGetSymbolAddress((void**)&Vhi, g_Vhi);
    cudaGetSymbolAddress((void**)&Vlo, g_Vlo);

    static bool attr_set = false;
    if (!attr_set) {
        cudaFuncSetAttribute(gemm_mma_bf16x3<0>,
                             cudaFuncAttributeMaxDynamicSharedMemorySize, GEMM_SMEM);
        cudaFuncSetAttribute(gemm_mma_bf16x3<1>,
                             cudaFuncAttributeMaxDynamicSharedMemorySize, GEMM_SMEM);
        cudaFuncSetAttribute(attn_mma,
                             cudaFuncAttributeMaxDynamicSharedMemorySize, ASMEM);
        attr_set = true;
    }

    // 1) split x into bf16 hi/lo
    {
        int n4 = MM * EE / 4;
        split_hi_lo<<<(n4 + 255) / 256, 256>>>((const float4*)x, (uint2*)xhi, (uint2*)xlo, n4);
    }
    // 2) transpose+split all weights
    const float* Ws[4] = {Wq, Wk, Wv, Wo};
    for (int i = 0; i < 4; i++)
        transpose_split<<<dim3(32, 32), dim3(32, 8)>>>(Ws[i], wthi + (size_t)i * EE * HDIM,
                                                       wtlo + (size_t)i * EE * HDIM);
    // 3) projections -> bf16 hi/lo in [b,h,c,d]; Q prescaled by 0.125*log2(e)
    dim3 ggrid(HDIM / 128, MM / 128);
    const float qscale = 0.125f * 1.4426950408889634f;
    gemm_mma_bf16x3<1><<<ggrid, 256, GEMM_SMEM>>>(
        xhi, xlo, wthi + 0 * (size_t)EE * HDIM, wtlo + 0 * (size_t)EE * HDIM,
        nullptr, Qhi, Qlo, qscale);
    gemm_mma_bf16x3<1><<<ggrid, 256, GEMM_SMEM>>>(
        xhi, xlo, wthi + 1 * (size_t)EE * HDIM, wtlo + 1 * (size_t)EE * HDIM,
        nullptr, Khi, Klo, 1.0f);
    gemm_mma_bf16x3<1><<<ggrid, 256, GEMM_SMEM>>>(
        xhi, xlo, wthi + 2 * (size_t)EE * HDIM, wtlo + 2 * (size_t)EE * HDIM,
        nullptr, Vhi, Vlo, 1.0f);

    // 4) attention -> hidden bf16 hi/lo [token, hdim]; 64 q-rows per CTA
    attn_mma<<<dim3(CC / 64, HH, BB), 128, ASMEM>>>(Qhi, Qlo, Khi, Klo, Vhi, Vlo, hhi, hlo);

    // 5) output projection -> fp32 out
    gemm_mma_bf16x3<0><<<ggrid, 256, GEMM_SMEM>>>(
        hhi, hlo, wthi + 3 * (size_t)EE * HDIM, wtlo + 3 * (size_t)EE * HDIM,
        out, nullptr, nullptr, 1.0f);
}

// round 7
// speedup vs baseline: 1.0512x; 1.0460x over previous
#include <cuda_runtime.h>
#include <cuda_bf16.h>
#include <cstdint>

// Problem constants
#define BB   4
#define CC   2048
#define EE   1024
#define HH   16
#define DD   64
#define HDIM 1024
#define MM   (BB*CC)        // 8192

// ---------------- scratch (device globals; no allocs allowed) ----------------
__device__ __nv_bfloat16 g_xhi[MM * EE];
__device__ __nv_bfloat16 g_xlo[MM * EE];
__device__ __nv_bfloat16 g_hhi[MM * HDIM];
__device__ __nv_bfloat16 g_hlo[MM * HDIM];
__device__ __nv_bfloat16 g_wthi[4][EE * HDIM];   // transposed weights [N,K] bf16 hi
__device__ __nv_bfloat16 g_wtlo[4][EE * HDIM];   // transposed weights [N,K] bf16 lo
// Q/K/V in [b, h, c, d] layout, bf16 hi/lo
__device__ __nv_bfloat16 g_Qhi[MM * HDIM];
__device__ __nv_bfloat16 g_Qlo[MM * HDIM];
__device__ __nv_bfloat16 g_Khi[MM * HDIM];
__device__ __nv_bfloat16 g_Klo[MM * HDIM];
__device__ __nv_bfloat16 g_Vhi[MM * HDIM];
__device__ __nv_bfloat16 g_Vlo[MM * HDIM];

// ---------------- helpers ----------------
__device__ __forceinline__ uint32_t smem_u32(const void* p) {
    uint32_t a;
    asm("{ .reg .u64 t; cvta.to.shared.u64 t, %1; cvt.u32.u64 %0, t; }" : "=r"(a) : "l"(p));
    return a;
}
__device__ __forceinline__ void cp_async16(uint32_t saddr, const void* gaddr) {
    asm volatile("cp.async.cg.shared.global [%0], [%1], 16;" :: "r"(saddr), "l"(gaddr));
}
#define CP_COMMIT() asm volatile("cp.async.commit_group;" ::: "memory")

__device__ __forceinline__ void ldsm4(uint32_t r[4], uint32_t addr) {
    asm volatile("ldmatrix.sync.aligned.m8n8.x4.shared.b16 {%0,%1,%2,%3}, [%4];"
                 : "=r"(r[0]), "=r"(r[1]), "=r"(r[2]), "=r"(r[3]) : "r"(addr));
}
__device__ __forceinline__ void ldsm4t(uint32_t r[4], uint32_t addr) {
    asm volatile("ldmatrix.sync.aligned.m8n8.x4.trans.shared.b16 {%0,%1,%2,%3}, [%4];"
                 : "=r"(r[0]), "=r"(r[1]), "=r"(r[2]), "=r"(r[3]) : "r"(addr));
}
__device__ __forceinline__ void mma16816(float c[4], const uint32_t a[4],
                                         uint32_t b0, uint32_t b1) {
    asm volatile(
        "mma.sync.aligned.m16n8k16.row.col.f32.bf16.bf16.f32 "
        "{%0,%1,%2,%3}, {%4,%5,%6,%7}, {%8,%9}, {%0,%1,%2,%3};"
        : "+f"(c[0]), "+f"(c[1]), "+f"(c[2]), "+f"(c[3])
        : "r"(a[0]), "r"(a[1]), "r"(a[2]), "r"(a[3]), "r"(b0), "r"(b1));
}
// pack two fp32 -> bf16x2 (first arg in low half)
__device__ __forceinline__ uint32_t packb(float lo, float hi) {
    uint32_t r;
    asm("cvt.rn.bf16x2.f32 %0, %1, %2;" : "=r"(r) : "f"(hi), "f"(lo));
    return r;
}
__device__ __forceinline__ float ublo(uint32_t u) { return __uint_as_float(u << 16); }
__device__ __forceinline__ float ubhi(uint32_t u) { return __uint_as_float(u & 0xffff0000u); }

// FMA-pipe exp2 (no MUFU): clamps at -126 (masked -1e30 -> ~1e-38 ~= 0).
__device__ __forceinline__ float fexp2(float x) {
    x = fmaxf(x, -126.0f);
    float fm = x + 12582912.0f;                 // 1.5 * 2^23 (rint magic)
    int ir = __float_as_int(fm) - 0x4b400000;
    float r = fm - 12582912.0f;
    float f = x - r;                            // [-0.5, 0.5]
    float p = 1.3333558146e-3f;
    p = fmaf(p, f, 9.6181291076e-3f);
    p = fmaf(p, f, 5.5504108665e-2f);
    p = fmaf(p, f, 2.4022650696e-1f);
    p = fmaf(p, f, 6.9314718056e-1f);
    p = fmaf(p, f, 1.0f);
    return __int_as_float(__float_as_int(p) + (ir << 23));
}

// ---------------------------------------------------------------------------
// Fused prep: slab 0 = split x into bf16 hi/lo; slabs 1-4 = transpose+split W.
// ---------------------------------------------------------------------------
#define XBLOCKS 8192                   // (MM*EE/4) / 256
__global__ __launch_bounds__(256) void prep_all(
    const float* __restrict__ x,
    const float* __restrict__ W0, const float* __restrict__ W1,
    const float* __restrict__ W2, const float* __restrict__ W3,
    __nv_bfloat16* __restrict__ xhi, __nv_bfloat16* __restrict__ xlo,
    __nv_bfloat16* __restrict__ wthi, __nv_bfloat16* __restrict__ wtlo) {
    const int tid = threadIdx.x;
    if (blockIdx.x < XBLOCKS) {
        const int i = blockIdx.x * 256 + tid;     // < MM*EE/4
        float4 v = ((const float4*)x)[i];
        uint32_t h0 = packb(v.x, v.y), h1 = packb(v.z, v.w);
        uint32_t l0 = packb(v.x - ublo(h0), v.y - ubhi(h0));
        uint32_t l1 = packb(v.z - ublo(h1), v.w - ubhi(h1));
        ((uint2*)xhi)[i] = make_uint2(h0, h1);
        ((uint2*)xlo)[i] = make_uint2(l0, l1);
        return;
    }
    __shared__ float t[32][33];
    const int sb2 = blockIdx.x - XBLOCKS;
    const int w = sb2 >> 10;                      // 0..3
    const int sub = sb2 & 1023;
    const float* W = (w == 0) ? W0 : (w == 1) ? W1 : (w == 2) ? W2 : W3;
    __nv_bfloat16* Thi = wthi + (size_t)w * EE * HDIM;
    __nv_bfloat16* Tlo = wtlo + (size_t)w * EE * HDIM;
    const int n0 = (sub & 31) * 32, k0 = (sub >> 5) * 32;
    const int tx = tid & 31, ty = tid >> 5;       // 32 x 8
#pragma unroll
    for (int r = ty; r < 32; r += 8)
        t[r][tx] = W[(size_t)(k0 + r) * 1024 + n0 + tx];
    __syncthreads();
#pragma unroll
    for (int r = ty; r < 32; r += 8) {
        float v = t[tx][r];
        __nv_bfloat16 h = __float2bfloat16(v);
        __nv_bfloat16 l = __float2bfloat16(v - __bfloat162float(h));
        size_t o = (size_t)(n0 + r) * 1024 + k0 + tx;
        Thi[o] = h; Tlo[o] = l;
    }
}

// ---------------------------------------------------------------------------
// mma.sync bf16x3 GEMM, 128x128 tile, BK=32, cp.async double buffer.
// MODE 0: C fp32 [M,1024].  MODE 1: bf16 hi/lo output in [b,h,c,d], scaled.
// ---------------------------------------------------------------------------
#define RSTR      80
#define MAT_BYTES (128 * RSTR)
#define STG_BYTES (4 * MAT_BYTES)
#define GEMM_SMEM (2 * STG_BYTES)
#define NCH       32

template <int MODE>
__global__ __launch_bounds__(256, 1) void gemm_mma_bf16x3(
    const __nv_bfloat16* __restrict__ Ahi, const __nv_bfloat16* __restrict__ Alo,
    const __nv_bfloat16* __restrict__ Bhi, const __nv_bfloat16* __restrict__ Blo,
    float* __restrict__ C, __nv_bfloat16* __restrict__ Ohi,
    __nv_bfloat16* __restrict__ Olo, float scale) {
    extern __shared__ char smem_raw[];
    const int tid = threadIdx.x;
    const int wid = tid >> 5, lane = tid & 31;
    const int brow = blockIdx.y * 128;
    const int bcol = blockIdx.x * 128;
    const uint32_t sbase = smem_u32(smem_raw);

    const int wm = (wid & 3) * 32;
    const int wn = (wid >> 2) * 64;

    const int l_row = tid >> 2;
    const int l_ch = tid & 3;
    auto load_stage = [&](int st, int kc) {
        const uint32_t so = sbase + st * STG_BYTES;
        const int k0 = kc * 32;
#pragma unroll
        for (int rep = 0; rep < 2; rep++) {
            const int row = rep * 64 + l_row;
            const uint32_t smoff = row * RSTR + l_ch * 16;
            const size_t ga = (size_t)(brow + row) * 1024 + k0 + l_ch * 8;
            const size_t gb = (size_t)(bcol + row) * 1024 + k0 + l_ch * 8;
            cp_async16(so + 0 * MAT_BYTES + smoff, Ahi + ga);
            cp_async16(so + 1 * MAT_BYTES + smoff, Alo + ga);
            cp_async16(so + 2 * MAT_BYTES + smoff, Bhi + gb);
            cp_async16(so + 3 * MAT_BYTES + smoff, Blo + gb);
        }
        CP_COMMIT();
    };

    float acc[2][8][4];
#pragma unroll
    for (int i = 0; i < 2; i++)
#pragma unroll
        for (int j = 0; j < 8; j++)
#pragma unroll
            for (int k = 0; k < 4; k++) acc[i][j][k] = 0.f;

    const int fr = lane & 15;
    const int fc = (lane >> 4) * 16;

    load_stage(0, 0);
    load_stage(1, 1);

    for (int c = 0; c < NCH; c++) {
        if (c < NCH - 1) asm volatile("cp.async.wait_group 1;" ::: "memory");
        else             asm volatile("cp.async.wait_group 0;" ::: "memory");
        __syncthreads();

        const uint32_t so = sbase + (c & 1) * STG_BYTES;
#pragma unroll
        for (int ks = 0; ks < 2; ks++) {
            uint32_t ah[2][4], al[2][4];
#pragma unroll
            for (int mt = 0; mt < 2; mt++) {
                const uint32_t ra = (wm + mt * 16 + fr) * RSTR + ks * 32 + fc;
                ldsm4(ah[mt], so + 0 * MAT_BYTES + ra);
                ldsm4(al[mt], so + 1 * MAT_BYTES + ra);
            }
            uint32_t bh[4][4], bl[4][4];
#pragma unroll
            for (int np = 0; np < 4; np++) {
                const uint32_t rb = (wn + np * 16 + fr) * RSTR + ks * 32 + fc;
                ldsm4(bh[np], so + 2 * MAT_BYTES + rb);
                ldsm4(bl[np], so + 3 * MAT_BYTES + rb);
            }
#pragma unroll
            for (int mt = 0; mt < 2; mt++) {
#pragma unroll
                for (int np = 0; np < 4; np++) {
                    mma16816(acc[mt][np * 2 + 0], ah[mt], bh[np][0], bh[np][2]);
                    mma16816(acc[mt][np * 2 + 0], ah[mt], bl[np][0], bl[np][2]);
                    mma16816(acc[mt][np * 2 + 0], al[mt], bh[np][0], bh[np][2]);
                    mma16816(acc[mt][np * 2 + 1], ah[mt], bh[np][1], bh[np][3]);
                    mma16816(acc[mt][np * 2 + 1], ah[mt], bl[np][1], bl[np][3]);
                    mma16816(acc[mt][np * 2 + 1], al[mt], bh[np][1], bh[np][3]);
                }
            }
        }
        __syncthreads();
        if (c + 2 < NCH) load_stage(c & 1, c + 2);
    }

#pragma unroll
    for (int mt = 0; mt < 2; mt++) {
#pragma unroll
        for (int nt = 0; nt < 8; nt++) {
            const int row = brow + wm + mt * 16 + (lane >> 2);
            const int col = bcol + wn + nt * 8 + (lane & 3) * 2;
            if (MODE == 0) {
                *(float2*)&C[(size_t)row * 1024 + col] =
                    make_float2(acc[mt][nt][0], acc[mt][nt][1]);
                *(float2*)&C[(size_t)(row + 8) * 1024 + col] =
                    make_float2(acc[mt][nt][2], acc[mt][nt][3]);
            } else {
                const int hh = col >> 6, dd = col & 63;
#pragma unroll
                for (int half = 0; half < 2; half++) {
                    const int r = row + half * 8;
                    const float v0 = acc[mt][nt][half * 2 + 0] * scale;
                    const float v1 = acc[mt][nt][half * 2 + 1] * scale;
                    const uint32_t hi = packb(v0, v1);
                    const uint32_t lo = packb(v0 - ublo(hi), v1 - ubhi(hi));
                    const int bb2 = r >> 11, cc2 = r & 2047;
                    const size_t off = (((size_t)(bb2 * HH + hh) * CC + cc2) * DD + dd);
                    *(uint32_t*)(Ohi + off) = hi;
                    *(uint32_t*)(Olo + off) = lo;
                }
            }
        }
    }
}

// ---------------------------------------------------------------------------
// Tensor-core causal flash attention, bf16x3, NO-MAX softmax (shift-invariant;
// scores bounded so exp2 cannot overflow fp32). Per-thread l accumulators,
// reduced once in epilogue. exp/pack interleaved with PV MMA per key group.
// CTA: 64 q rows, 4 warps x 16 rows, 128 threads, 2 CTAs/SM.
// ---------------------------------------------------------------------------
#define ATS    144                 // bytes per smem row (64 bf16 + 16B pad)
#define ATILE  (64 * ATS)          // 9216
#define ASTAGE (4 * ATILE)         // Khi|Klo|Vhi|Vlo = 36864
#define ASMEM  (2 * ASTAGE)        // 73728

__global__ __launch_bounds__(128, 2) void attn_mma(
    const __nv_bfloat16* __restrict__ Qhi, const __nv_bfloat16* __restrict__ Qlo,
    const __nv_bfloat16* __restrict__ Khi, const __nv_bfloat16* __restrict__ Klo,
    const __nv_bfloat16* __restrict__ Vhi, const __nv_bfloat16* __restrict__ Vlo,
    __nv_bfloat16* __restrict__ Ohi, __nv_bfloat16* __restrict__ Olo) {
    extern __shared__ char smem_raw[];
    const uint32_t sb = smem_u32(smem_raw);
    const int tid = threadIdx.x, wid = tid >> 5, lane = tid & 31;
    const int qt = (gridDim.x - 1) - blockIdx.x;   // biggest tiles launch first
    const int h = blockIdx.y, b = blockIdx.z;
    const int q0 = qt * 64;
    const size_t bh = (size_t)(b * HH + h) * CC * DD;

    const int fr = lane & 15, fcb = (lane >> 4) * 16;

    // ---- Q tile (64 rows) into stage-0 region (hi at sb, lo at sb + 64*ATS) ----
    {
        const __nv_bfloat16* qh = Qhi + bh + (size_t)q0 * DD;
        const __nv_bfloat16* ql = Qlo + bh + (size_t)q0 * DD;
#pragma unroll
        for (int i = 0; i < 4; i++) {
            const int id = i * 128 + tid;       // 0..511
            const int r = id >> 3, ch = id & 7;
            cp_async16(sb + r * ATS + ch * 16, qh + r * 64 + ch * 8);
            cp_async16(sb + 64 * ATS + r * ATS + ch * 16, ql + r * 64 + ch * 8);
        }
        CP_COMMIT();
        asm volatile("cp.async.wait_group 0;" ::: "memory");
        __syncthreads();
    }
    uint32_t qfh[4][4], qfl[4][4];
#pragma unroll
    for (int ks = 0; ks < 4; ks++) {
        const uint32_t a = sb + (wid * 16 + fr) * ATS + ks * 32 + fcb;
        ldsm4(qfh[ks], a);
        ldsm4(qfl[ks], a + 64 * ATS);
    }
    __syncthreads();

    float o[8][4];
#pragma unroll
    for (int j = 0; j < 8; j++)
#pragma unroll
        for (int k = 0; k < 4; k++) o[j][k] = 0.f;
    float l0 = 0.f, l1 = 0.f;                    // per-thread softmax denominators

    const int nt = qt + 1;                       // keys 0 .. q0+63
    const int rowmax = q0 + wid * 16 + 15;       // warp-uniform max q row

    auto load_kv = [&](int t, int stage) {
        const uint32_t st = sb + stage * ASTAGE;
        const int k0 = t * 64;
#pragma unroll
        for (int i = 0; i < 4; i++) {
            const int id = i * 128 + tid;        // 0..511
            const int r = id >> 3, ch = id & 7;
            const size_t g = bh + (size_t)(k0 + r) * 64 + ch * 8;
            const uint32_t so = r * ATS + ch * 16;
            cp_async16(st + 0 * ATILE + so, Khi + g);
            cp_async16(st + 1 * ATILE + so, Klo + g);
            cp_async16(st + 2 * ATILE + so, Vhi + g);
            cp_async16(st + 3 * ATILE + so, Vlo + g);
        }
        CP_COMMIT();
    };

    load_kv(0, 0);
    if (nt > 1) load_kv(1, 1);

    for (int t = 0; t < nt; t++) {
        if (t + 1 < nt) asm volatile("cp.async.wait_group 1;" ::: "memory");
        else            asm volatile("cp.async.wait_group 0;" ::: "memory");
        __syncthreads();

        const uint32_t st = sb + (t & 1) * ASTAGE;
        const bool masked = (t == qt);
        const int k0g = t * 64;

        float s[8][4];
#pragma unroll
        for (int j = 0; j < 8; j++)
#pragma unroll
            for (int k = 0; k < 4; k++) s[j][k] = 0.f;

        // ---- S = Q @ K^T (x3 compensated), skipping fully-masked key blocks ----
#pragma unroll
        for (int np = 0; np < 4; np++) {
            if (masked && (k0g + np * 16 > rowmax)) continue;
#pragma unroll
            for (int ks = 0; ks < 4; ks++) {
                const uint32_t addr = st + (np * 16 + fr) * ATS + ks * 32 + fcb;
                uint32_t kh[4], kl[4];
                ldsm4(kh, addr);
                ldsm4(kl, addr + ATILE);
                mma16816(s[np * 2 + 0], qfh[ks], kh[0], kh[2]);
                mma16816(s[np * 2 + 0], qfh[ks], kl[0], kl[2]);
                mma16816(s[np * 2 + 0], qfl[ks], kh[0], kh[2]);
                mma16816(s[np * 2 + 1], qfh[ks], kh[1], kh[3]);
                mma16816(s[np * 2 + 1], qfh[ks], kl[1], kl[3]);
                mma16816(s[np * 2 + 1], qfl[ks], kh[1], kh[3]);
            }
        }

        if (masked) {
            const int row0 = q0 + wid * 16 + (lane >> 2);
            const int kc0 = k0g + (lane & 3) * 2;
#pragma unroll
            for (int np8 = 0; np8 < 8; np8++) {
                const int kc = kc0 + np8 * 8;
                if (kc > row0)         s[np8][0] = -1e30f;
                if (kc + 1 > row0)     s[np8][1] = -1e30f;
                if (kc > row0 + 8)     s[np8][2] = -1e30f;
                if (kc + 1 > row0 + 8) s[np8][3] = -1e30f;
            }
        }

        // ---- NO-MAX softmax + PV interleaved per 16-key group ----
#pragma unroll
        for (int ks = 0; ks < 4; ks++) {
            if (masked && (k0g + ks * 16 > rowmax)) continue;
            const int e = 2 * ks, d = 2 * ks + 1;
            s[e][0] = fexp2(s[e][0]); s[e][1] = fexp2(s[e][1]);
            s[e][2] = fexp2(s[e][2]); s[e][3] = fexp2(s[e][3]);
            s[d][0] = fexp2(s[d][0]); s[d][1] = fexp2(s[d][1]);
            s[d][2] = fexp2(s[d][2]); s[d][3] = fexp2(s[d][3]);
            l0 += s[e][0] + s[e][1] + s[d][0] + s[d][1];
            l1 += s[e][2] + s[e][3] + s[d][2] + s[d][3];

            uint32_t pfh[4], pfl[4];
            pfh[0] = packb(s[e][0], s[e][1]);
            pfh[1] = packb(s[e][2], s[e][3]);
            pfh[2] = packb(s[d][0], s[d][1]);
            pfh[3] = packb(s[d][2], s[d][3]);
            pfl[0] = packb(s[e][0] - ublo(pfh[0]), s[e][1] - ubhi(pfh[0]));
            pfl[1] = packb(s[e][2] - ublo(pfh[1]), s[e][3] - ubhi(pfh[1]));
            pfl[2] = packb(s[d][0] - ublo(pfh[2]), s[d][1] - ubhi(pfh[2]));
            pfl[3] = packb(s[d][2] - ublo(pfh[3]), s[d][3] - ubhi(pfh[3]));

#pragma unroll
            for (int np = 0; np < 4; np++) {
                const uint32_t addr =
                    st + 2 * ATILE + (ks * 16 + fr) * ATS + np * 32 + fcb;
                uint32_t vh[4], vl[4];
                ldsm4t(vh, addr);
                ldsm4t(vl, addr + ATILE);
                mma16816(o[np * 2 + 0], pfh, vh[0], vh[1]);
                mma16816(o[np * 2 + 0], pfh, vl[0], vl[1]);
                mma16816(o[np * 2 + 0], pfl, vh[0], vh[1]);
                mma16816(o[np * 2 + 1], pfh, vh[2], vh[3]);
                mma16816(o[np * 2 + 1], pfh, vl[2], vl[3]);
                mma16816(o[np * 2 + 1], pfl, vh[2], vh[3]);
            }
        }
        __syncthreads();
        if (t + 2 < nt) load_kv(t + 2, t & 1);
    }

    // ---- epilogue: reduce l across quad lanes, normalize, split hi/lo, store ----
    l0 += __shfl_xor_sync(0xffffffffu, l0, 1);
    l0 += __shfl_xor_sync(0xffffffffu, l0, 2);
    l1 += __shfl_xor_sync(0xffffffffu, l1, 1);
    l1 += __shfl_xor_sync(0xffffffffu, l1, 2);
    const float inv0 = 1.0f / l0;
    const float inv1 = 1.0f / l1;
    const int row = q0 + wid * 16 + (lane >> 2);
#pragma unroll
    for (int np8 = 0; np8 < 8; np8++) {
        const int col = np8 * 8 + (lane & 3) * 2;
        const size_t off0 = (size_t)(b * CC + row) * HDIM + h * 64 + col;
        const size_t off8 = off0 + (size_t)8 * HDIM;
        float v0 = o[np8][0] * inv0, v1 = o[np8][1] * inv0;
        float v2 = o[np8][2] * inv1, v3 = o[np8][3] * inv1;
        uint32_t hi0 = packb(v0, v1);
        uint32_t lo0 = packb(v0 - ublo(hi0), v1 - ubhi(hi0));
        uint32_t hi8 = packb(v2, v3);
        uint32_t lo8 = packb(v2 - ublo(hi8), v3 - ubhi(hi8));
        *(uint32_t*)(Ohi + off0) = hi0;
        *(uint32_t*)(Olo + off0) = lo0;
        *(uint32_t*)(Ohi + off8) = hi8;
        *(uint32_t*)(Olo + off8) = lo8;
    }
}

// ---------------------------------------------------------------------------
extern "C" void kernel_launch(void* const* d_in, const int* in_sizes, int n_in,
                              void* d_out, int out_size) {
    const float* x  = (const float*)d_in[0];
    const float* Wq = (const float*)d_in[1];
    const float* Wk = (const float*)d_in[2];
    const float* Wv = (const float*)d_in[3];
    const float* Wo = (const float*)d_in[4];
    float* out = (float*)d_out;

    __nv_bfloat16 *xhi, *xlo, *hhi, *hlo, *wthi, *wtlo;
    __nv_bfloat16 *Qhi, *Qlo, *Khi, *Klo, *Vhi, *Vlo;
    cudaGetSymbolAddress((void**)&xhi, g_xhi);
    cudaGetSymbolAddress((void**)&xlo, g_xlo);
    cudaGetSymbolAddress((void**)&hhi, g_hhi);
    cudaGetSymbolAddress((void**)&hlo, g_hlo);
    cudaGetSymbolAddress((void**)&wthi, g_wthi);
    cudaGetSymbolAddress((void**)&wtlo, g_wtlo);
    cudaGetSymbolAddress((void**)&Qhi, g_Qhi);
    cudaGetSymbolAddress((void**)&Qlo, g_Qlo);
    cudaGetSymbolAddress((void**)&Khi, g_Khi);
    cudaGetSymbolAddress((void**)&Klo, g_Klo);
    cudaGetSymbolAddress((void**)&Vhi, g_Vhi);
    cudaGetSymbolAddress((void**)&Vlo, g_Vlo);

    static bool attr_set = false;
    if (!attr_set) {
        cudaFuncSetAttribute(gemm_mma_bf16x3<0>,
                             cudaFuncAttributeMaxDynamicSharedMemorySize, GEMM_SMEM);
        cudaFuncSetAttribute(gemm_mma_bf16x3<1>,
                             cudaFuncAttributeMaxDynamicSharedMemorySize, GEMM_SMEM);
        cudaFuncSetAttribute(attn_mma,
                             cudaFuncAttributeMaxDynamicSharedMemorySize, ASMEM);
        attr_set = true;
    }

    // 0) fused prep: x split + 4 weight transposes (one launch)
    prep_all<<<XBLOCKS + 4 * 1024, 256>>>(x, Wq, Wk, Wv, Wo, xhi, xlo, wthi, wtlo);

    // 1-3) projections -> bf16 hi/lo in [b,h,c,d]; Q prescaled by 0.125*log2(e)
    dim3 ggrid(HDIM / 128, MM / 128);
    const float qscale = 0.125f * 1.4426950408889634f;
    gemm_mma_bf16x3<1><<<ggrid, 256, GEMM_SMEM>>>(
        xhi, xlo, wthi + 0 * (size_t)EE * HDIM, wtlo + 0 * (size_t)EE * HDIM,
        nullptr, Qhi, Qlo, qscale);
    gemm_mma_bf16x3<1><<<ggrid, 256, GEMM_SMEM>>>(
        xhi, xlo, wthi + 1 * (size_t)EE * HDIM, wtlo + 1 * (size_t)EE * HDIM,
        nullptr, Khi, Klo, 1.0f);
    gemm_mma_bf16x3<1><<<ggrid, 256, GEMM_SMEM>>>(
        xhi, xlo, wthi + 2 * (size_t)EE * HDIM, wtlo + 2 * (size_t)EE * HDIM,
        nullptr, Vhi, Vlo, 1.0f);

    // 4) attention -> hidden bf16 hi/lo [token, hdim]; 64 q-rows per CTA
    attn_mma<<<dim3(CC / 64, HH, BB), 128, ASMEM>>>(Qhi, Qlo, Khi, Klo, Vhi, Vlo, hhi, hlo);

    // 5) output projection -> fp32 out (hidden already bf16 hi/lo from attention)
    gemm_mma_bf16x3<0><<<ggrid, 256, GEMM_SMEM>>>(
        hhi, hlo, wthi + 3 * (size_t)EE * HDIM, wtlo + 3 * (size_t)EE * HDIM,
        out, nullptr, nullptr, 1.0f);
}